// round 12
// baseline (speedup 1.0000x reference)
#include <cuda_runtime.h>
#include <cuda_fp16.h>
#include <math.h>

#define NN 50000
#define EE 800000
#define DD 512
#define EBLK 3125   // edge blocks in merged kernel (EE/256)

// ---------------- scratch (device globals; no allocations) ----------------
__device__ __align__(16) __half g_xh[(size_t)NN * DD];    // x in fp16
__device__ __align__(16) __half g_aggh[(size_t)NN * DD];  // aggregated, fp16
__device__ __align__(16) __half g_wh[512 * 512];          // W in fp16
__device__ __align__(16) float g_deg[NN];
__device__ __align__(16) float g_dinv[NN];
__device__ __align__(16) __half g_ew[EE];                 // edge confidence fp16
__device__ __align__(16) unsigned g_rc[EE];               // (col<<16)|row
__device__ int      g_cnt[NN];
__device__ int      g_off[NN];
__device__ int      g_cur[NN];
__device__ unsigned g_epack[EE];      // (ew_fp16 << 16) | src_row
__device__ unsigned g_tstate[128];    // lookback state
__device__ int      g_ticket;
__device__ int      g_idx64;

#define SCAN_B 512
#define NBLK   98

// ---------------- edge-index dtype-agnostic fetch ----------------
__device__ __forceinline__ long long edge_idx(const void* p, long long i) {
    if (g_idx64) return ((const long long*)p)[i];
    return (long long)((const int*)p)[i];
}

__device__ __forceinline__ uint4 cvt8(float4 f0, float4 f1) {
    uint4 o;
    __half2* oh = (__half2*)&o;
    oh[0] = __float22half2_rn(make_float2(f0.x, f0.y));
    oh[1] = __float22half2_rn(make_float2(f0.z, f0.w));
    oh[2] = __float22half2_rn(make_float2(f1.x, f1.y));
    oh[3] = __float22half2_rn(make_float2(f1.z, f1.w));
    return o;
}

// Edge-chain head: detect idx dtype, zero counters and scan state.
__global__ void prep_meta(const void* __restrict__ ei) {
    int i = blockIdx.x * blockDim.x + threadIdx.x;
    if (i == 0) {
        const long long* p = (const long long*)ei;
        int ok = 1;
        for (int j = 0; j < 64; j++) {
            long long v = p[j];
            if (v < 0 || v >= NN) { ok = 0; break; }
        }
        g_idx64 = ok;
        g_ticket = 0;
    }
    if (i < 128) g_tstate[i] = 0;
    if (i < NN) { g_deg[i] = 0.f; g_cnt[i] = 0; }
}

// Merged: edge pass (blocks [0, EBLK)) + fp16 conversion (remaining blocks).
// In-kernel overlap of atomic/latency-bound edge work with DRAM streaming.
__global__ void edge_conv(const void* __restrict__ ei,
                          const float* __restrict__ ea,
                          const float* __restrict__ cw,
                          const float* __restrict__ cb,
                          const float* __restrict__ x,
                          const float* __restrict__ W) {
    int b = blockIdx.x;
    if (b < EBLK) {
        int e = b * 256 + threadIdx.x;
        if (e >= EE) return;
        long long r = edge_idx(ei, e);
        long long c = edge_idx(ei, (long long)EE + e);
        atomicAdd(&g_deg[r], 1.0f);
        atomicAdd(&g_cnt[c], 1);
        g_rc[e] = ((unsigned)c << 16) | (unsigned)r;
        float z = ea[e * 3 + 0] * cw[0] + ea[e * 3 + 1] * cw[1]
                + ea[e * 3 + 2] * cw[2] + cb[0];
        g_ew[e] = __float2half(1.0f / (1.0f + expf(-z)));
    } else {
        size_t i = (size_t)(b - EBLK) * 256 + threadIdx.x;
        if (i < 512 * 512 / 8)
            ((uint4*)g_wh)[i] = cvt8(((const float4*)W)[i * 2], ((const float4*)W)[i * 2 + 1]);
        if (i < (size_t)NN * DD / 8)
            ((uint4*)g_xh)[i] = cvt8(((const float4*)x)[i * 2], ((const float4*)x)[i * 2 + 1]);
    }
}

// Single-launch decoupled-lookback scan; fuses node_dinv + cursor init.
__global__ __launch_bounds__(SCAN_B) void scan_all() {
    __shared__ int s[SCAN_B];
    __shared__ int sbid, sprev;
    const int tid = threadIdx.x;
    if (tid == 0) sbid = atomicAdd(&g_ticket, 1);
    __syncthreads();
    const int bid = sbid;
    const int i = bid * SCAN_B + tid;

    int v = (i < NN) ? g_cnt[i] : 0;
    if (i < NN) {
        float d = g_deg[i];
        g_dinv[i] = (d > 0.f) ? rsqrtf(d) : 0.f;
    }
    s[tid] = v;
    __syncthreads();
    for (int off = 1; off < SCAN_B; off <<= 1) {
        int t = (tid >= off) ? s[tid - off] : 0;
        __syncthreads();
        s[tid] += t;
        __syncthreads();
    }
    const int aggv = s[SCAN_B - 1];

    if (tid == 0) {
        if (bid == 0) {
            atomicExch(&g_tstate[0], (2u << 30) | (unsigned)aggv);
            sprev = 0;
        } else {
            atomicExch(&g_tstate[bid], (1u << 30) | (unsigned)aggv);
            int run = 0;
            for (int t = bid - 1; t >= 0; t--) {
                unsigned st;
                do { st = atomicOr(&g_tstate[t], 0u); } while ((st >> 30) == 0u);
                run += (int)(st & 0x3FFFFFFFu);
                if ((st >> 30) == 2u) break;
            }
            atomicExch(&g_tstate[bid], (2u << 30) | (unsigned)(run + aggv));
            sprev = run;
        }
    }
    __syncthreads();
    if (i < NN) {
        int off = sprev + s[tid] - v;
        g_off[i] = off;
        g_cur[i] = off;
    }
}

// Fill CSR payload from packed rc.
__global__ void fill_kernel() {
    int e = blockIdx.x * blockDim.x + threadIdx.x;
    if (e >= EE) return;
    unsigned rc = g_rc[e];
    unsigned ew = (unsigned)__half_as_ushort(g_ew[e]);
    int p = atomicAdd(&g_cur[rc >> 16], 1);
    g_epack[p] = (ew << 16) | (rc & 0xFFFFu);
}

__device__ __forceinline__ void acc8(float2* acc, uint4 v, float nm) {
    const __half2* h = (const __half2*)&v;
    #pragma unroll
    for (int q = 0; q < 4; q++) {
        float2 f = __half22float2(h[q]);
        acc[q].x += f.x * nm;
        acc[q].y += f.y * nm;
    }
}

// Gather aggregation: one WARP per node, batch-level software pipelining.
__global__ __launch_bounds__(256) void agg_kernel() {
    int warp = threadIdx.x >> 5;
    int lane = threadIdx.x & 31;
    int n = blockIdx.x * 8 + warp;
    if (n >= NN) return;
    int start = g_off[n];
    int cnt   = g_cnt[n];
    float dsn = g_dinv[n];

    float2 accA[4] = {{0.f,0.f},{0.f,0.f},{0.f,0.f},{0.f,0.f}};
    float2 accB[4] = {{0.f,0.f},{0.f,0.f},{0.f,0.f},{0.f,0.f}};

    unsigned pk = 0;
    if (lane < cnt) pk = g_epack[start + lane];

    for (int base = 0; base < cnt; base += 32) {
        int m = min(32, cnt - base);
        float val = 0.f;
        if (lane < m)
            val = g_dinv[pk & 0xFFFFu]
                * __half2float(__ushort_as_half((unsigned short)(pk >> 16)));
        unsigned pkc = pk;
        pk = 0;
        if (base + 32 + lane < cnt) pk = g_epack[start + base + 32 + lane];

        #pragma unroll 4
        for (int j = 0; j < m; j++) {
            unsigned p = __shfl_sync(0xffffffffu, pkc, j);
            float nm = __shfl_sync(0xffffffffu, val, j) * dsn;
            int r = (int)(p & 0xFFFFu);
            const uint4* xp = (const uint4*)(g_xh + (size_t)r * DD) + lane;
            uint4 v0 = xp[0];
            uint4 v1 = xp[32];
            acc8(accA, v0, nm);
            acc8(accB, v1, nm);
        }
    }
    uint4 o0, o1;
    __half2* h0 = (__half2*)&o0;
    __half2* h1 = (__half2*)&o1;
    #pragma unroll
    for (int q = 0; q < 4; q++) {
        h0[q] = __float22half2_rn(accA[q]);
        h1[q] = __float22half2_rn(accB[q]);
    }
    uint4* op = (uint4*)(g_aggh + (size_t)n * DD) + lane;
    __stcs(op, o0);
    __stcs(op + 32, o1);
}

// ---------------- fp16 tensor-core GEMM: C = A @ W^T + bias ----------------
// Persistent-A: the full 128x512 A tile lives in smem (loaded once); N=512
// processed as two sequential 256-col halves with one continuous 32-chunk
// 3-stage cp.async B pipeline (no drain at the half boundary).
__device__ __forceinline__ void mma_f16(float* d, const unsigned* a, const unsigned* b) {
    asm volatile(
        "mma.sync.aligned.m16n8k16.row.col.f32.f16.f16.f32 "
        "{%0,%1,%2,%3}, {%4,%5,%6,%7}, {%8,%9}, {%0,%1,%2,%3};"
        : "+f"(d[0]), "+f"(d[1]), "+f"(d[2]), "+f"(d[3])
        : "r"(a[0]), "r"(a[1]), "r"(a[2]), "r"(a[3]), "r"(b[0]), "r"(b[1]));
}
__device__ __forceinline__ void ldm_x4(unsigned& r0, unsigned& r1,
                                       unsigned& r2, unsigned& r3, unsigned addr) {
    asm volatile("ldmatrix.sync.aligned.m8n8.x4.shared.b16 {%0,%1,%2,%3}, [%4];"
                 : "=r"(r0), "=r"(r1), "=r"(r2), "=r"(r3) : "r"(addr));
}
__device__ __forceinline__ void cpa16(unsigned dst, const void* src, int sz) {
    asm volatile("cp.async.cg.shared.global [%0], [%1], 16, %2;"
                 :: "r"(dst), "l"(src), "r"(sz) : "memory");
}
__device__ __forceinline__ unsigned smem_u32(const void* p) {
    unsigned a;
    asm("{ .reg .u64 t; cvta.to.shared.u64 t, %1; cvt.u32.u64 %0, t; }" : "=r"(a) : "l"(p));
    return a;
}

#define A_PITCH 520                   // 512 + 8 pad halves; row stride 1040 B
#define KPH 40                        // B: 32 k + 8 pad
#define SM_A_H (128 * A_PITCH)        // 66560 halves
#define B_ST (256 * KPH)              // 10240 halves per stage
#define GSMEM ((SM_A_H + 3 * B_ST) * 2)   // 194560 B

__global__ __launch_bounds__(256, 1) void gemm_f16(const float* __restrict__ bias,
                                                   float* __restrict__ C,
                                                   int M) {
    extern __shared__ __half sm[];
    const unsigned smb = smem_u32(sm);

    const int tid  = threadIdx.x;
    const int lane = tid & 31;
    const int warp = tid >> 5;
    const int wm = warp & 1;
    const int wn = warp >> 1;
    const int g  = lane >> 2;
    const int tg = lane & 3;

    const int blockRow = blockIdx.x * 128;

    // ldmatrix per-lane address components
    const int aRowOff = (lane & 7) + ((lane >> 3) & 1) * 8;  // 0..15
    const int aKOff   = (lane >> 4) * 8;                     // 0/8
    const int bColOff = (lane & 7);
    const int bKOff   = ((lane >> 3) & 1) * 8;               // 0/8
    const int bNtHalf = (lane >> 4);                         // 0/1

    const int lr  = tid >> 1;
    const int c0h = (tid & 1) * 256;     // A loader: 2 threads/row, 256 halves each
    const int gr  = blockRow + lr;
    const int aSz = (gr < M) ? 16 : 0;
    const __half* aSrc = g_aggh + (size_t)min(gr, M - 1) * 512 + c0h;
    const __half* bSrc = g_wh + (size_t)tid * 512;   // row = tid (cols via q)

    // ---- prologue: load the full A tile (one commit group) ----
    {
        unsigned ad = smb + (unsigned)(lr * A_PITCH + c0h) * 2;
        #pragma unroll
        for (int j = 0; j < 32; j++)
            cpa16(ad + j * 16, aSrc + j * 8, aSz);
        asm volatile("cp.async.commit_group;" ::: "memory");
    }

    // B chunk q = nh*16 + ch: cols (q>>4)*256 + [0,256), k = (q&15)*32
    auto load_b = [&](int q) {
        unsigned bb = smb + (unsigned)(SM_A_H + (q % 3) * B_ST) * 2;
        const __half* bp = bSrc + (size_t)(q >> 4) * 256 * 512 + (q & 15) * 32;
        #pragma unroll
        for (int j = 0; j < 4; j++)
            cpa16(bb + (unsigned)(tid * KPH + j * 8) * 2, bp + j * 8, 16);
        asm volatile("cp.async.commit_group;" ::: "memory");
    };
    load_b(0);
    load_b(1);

    float acc[4][8][4];
    #pragma unroll
    for (int mt = 0; mt < 4; mt++)
        #pragma unroll
        for (int nt = 0; nt < 8; nt++)
            #pragma unroll
            for (int q = 0; q < 4; q++) acc[mt][nt][q] = 0.f;

    for (int q = 0; q < 32; q++) {
        if (q + 2 < 32) asm volatile("cp.async.wait_group 1;" ::: "memory");
        else            asm volatile("cp.async.wait_group 0;" ::: "memory");
        __syncthreads();
        if (q + 2 < 32) load_b(q + 2);

        const unsigned bsb = smb + (unsigned)(SM_A_H + (q % 3) * B_ST) * 2;
        const int kk = (q & 15) * 32;

        #pragma unroll
        for (int ks = 0; ks < 32; ks += 16) {
            unsigned a[4][4], bf[8][2];
            #pragma unroll
            for (int mt = 0; mt < 4; mt++) {
                unsigned addr = smb + (unsigned)(((wm * 64 + mt * 16 + aRowOff) * A_PITCH
                                                 + kk + ks + aKOff) * 2);
                ldm_x4(a[mt][0], a[mt][1], a[mt][2], a[mt][3], addr);
            }
            #pragma unroll
            for (int p = 0; p < 4; p++) {
                int col = wn * 64 + (2 * p + bNtHalf) * 8 + bColOff;
                unsigned addr = bsb + (unsigned)((col * KPH + ks + bKOff) * 2);
                unsigned r0, r1, r2, r3;
                ldm_x4(r0, r1, r2, r3, addr);
                bf[2 * p][0] = r0; bf[2 * p][1] = r1;
                bf[2 * p + 1][0] = r2; bf[2 * p + 1][1] = r3;
            }
            #pragma unroll
            for (int mt = 0; mt < 4; mt++)
                #pragma unroll
                for (int nt = 0; nt < 8; nt++)
                    mma_f16(acc[mt][nt], a[mt], bf[nt]);
        }
        __syncthreads();

        // epilogue at the end of each half; reset accumulators
        if ((q & 15) == 15) {
            const int blockCol = (q >> 4) * 256;
            #pragma unroll
            for (int mt = 0; mt < 4; mt++) {
                int r0 = blockRow + wm * 64 + mt * 16 + g;
                #pragma unroll
                for (int nt = 0; nt < 8; nt++) {
                    int col = blockCol + wn * 64 + nt * 8 + tg * 2;
                    float b0 = bias[col], b1 = bias[col + 1];
                    if (r0 < M) {
                        float2 o = make_float2(acc[mt][nt][0] + b0, acc[mt][nt][1] + b1);
                        *(float2*)(C + (size_t)r0 * 512 + col) = o;
                    }
                    if (r0 + 8 < M) {
                        float2 o = make_float2(acc[mt][nt][2] + b0, acc[mt][nt][3] + b1);
                        *(float2*)(C + (size_t)(r0 + 8) * 512 + col) = o;
                    }
                    #pragma unroll
                    for (int z = 0; z < 4; z++) acc[mt][nt][z] = 0.f;
                }
            }
        }
    }
}

extern "C" void kernel_launch(void* const* d_in, const int* in_sizes, int n_in,
                              void* d_out, int out_size) {
    const float* x  = (const float*)d_in[0];
    const void*  ei = d_in[1];
    const float* ea = (const float*)d_in[2];
    const float* lw = (const float*)d_in[3];
    const float* lb = (const float*)d_in[4];
    const float* cw = (const float*)d_in[5];
    const float* cb = (const float*)d_in[6];
    float* out = (float*)d_out;

    cudaFuncSetAttribute(gemm_f16, cudaFuncAttributeMaxDynamicSharedMemorySize, GSMEM);

    prep_meta<<<(NN + 255) / 256, 256>>>(ei);
    edge_conv<<<EBLK + (NN * DD / 8 + 255) / 256, 256>>>(ei, ea, cw, cb, x, lw);
    scan_all<<<NBLK, SCAN_B>>>();
    fill_kernel<<<(EE + 255) / 256, 256>>>();
    agg_kernel<<<(NN + 7) / 8, 256>>>();

    gemm_f16<<<(NN + 127) / 128, 256, GSMEM>>>(lb, out, NN);
}

// round 13
// speedup vs baseline: 1.0153x; 1.0153x over previous
#include <cuda_runtime.h>
#include <cuda_fp16.h>
#include <math.h>

#define NN 50000
#define EE 800000
#define DD 512

// ---------------- scratch (device globals; no allocations) ----------------
__device__ __align__(16) __half g_xh[(size_t)NN * DD];    // x in fp16
__device__ __align__(16) __half g_aggh[(size_t)NN * DD];  // aggregated, fp16
__device__ __align__(16) __half g_wh[512 * 512];          // W in fp16
__device__ __align__(16) float g_deg[NN];
__device__ __align__(16) float g_dinv[NN];
__device__ __align__(16) __half g_ew[EE];                 // edge confidence fp16
__device__ __align__(16) unsigned g_rc[EE];               // (col<<16)|row
__device__ int      g_cnt[NN];
__device__ int      g_off[NN];
__device__ int      g_cur[NN];
__device__ unsigned g_epack[EE];      // (ew_fp16 << 16) | src_row
__device__ unsigned g_tstate[128];    // lookback state
__device__ int      g_ticket;        // scan ticket
__device__ int      g_aticket;       // agg work-stealing ticket
__device__ int      g_idx64;

#define SCAN_B 512
#define NBLK   98

// ---------------- edge-index dtype-agnostic fetch ----------------
__device__ __forceinline__ long long edge_idx(const void* p, long long i) {
    if (g_idx64) return ((const long long*)p)[i];
    return (long long)((const int*)p)[i];
}

__device__ __forceinline__ uint4 cvt8(float4 f0, float4 f1) {
    uint4 o;
    __half2* oh = (__half2*)&o;
    oh[0] = __float22half2_rn(make_float2(f0.x, f0.y));
    oh[1] = __float22half2_rn(make_float2(f0.z, f0.w));
    oh[2] = __float22half2_rn(make_float2(f1.x, f1.y));
    oh[3] = __float22half2_rn(make_float2(f1.z, f1.w));
    return o;
}

// Convert x and W to fp16.
__global__ void prep_convert(const float* __restrict__ x, const float* __restrict__ W) {
    size_t i = (size_t)blockIdx.x * blockDim.x + threadIdx.x;
    if (i < 512 * 512 / 8)
        ((uint4*)g_wh)[i] = cvt8(((const float4*)W)[i * 2], ((const float4*)W)[i * 2 + 1]);
    if (i < (size_t)NN * DD / 8)
        ((uint4*)g_xh)[i] = cvt8(((const float4*)x)[i * 2], ((const float4*)x)[i * 2 + 1]);
}

// Edge-chain head: detect idx dtype, zero counters and scan state.
__global__ void prep_meta(const void* __restrict__ ei) {
    int i = blockIdx.x * blockDim.x + threadIdx.x;
    if (i == 0) {
        const long long* p = (const long long*)ei;
        int ok = 1;
        for (int j = 0; j < 64; j++) {
            long long v = p[j];
            if (v < 0 || v >= NN) { ok = 0; break; }
        }
        g_idx64 = ok;
        g_ticket = 0;
        g_aticket = 0;
    }
    if (i < 128) g_tstate[i] = 0;
    if (i < NN) { g_deg[i] = 0.f; g_cnt[i] = 0; }
}

__global__ void edge_pass1(const void* __restrict__ ei,
                           const float* __restrict__ ea,
                           const float* __restrict__ cw,
                           const float* __restrict__ cb) {
    int e = blockIdx.x * blockDim.x + threadIdx.x;
    if (e >= EE) return;
    long long r = edge_idx(ei, e);
    long long c = edge_idx(ei, (long long)EE + e);
    atomicAdd(&g_deg[r], 1.0f);
    atomicAdd(&g_cnt[c], 1);
    g_rc[e] = ((unsigned)c << 16) | (unsigned)r;
    float z = ea[e * 3 + 0] * cw[0] + ea[e * 3 + 1] * cw[1]
            + ea[e * 3 + 2] * cw[2] + cb[0];
    g_ew[e] = __float2half(1.0f / (1.0f + expf(-z)));
}

// Single-launch decoupled-lookback scan; fuses node_dinv + cursor init.
__global__ __launch_bounds__(SCAN_B) void scan_all() {
    __shared__ int s[SCAN_B];
    __shared__ int sbid, sprev;
    const int tid = threadIdx.x;
    if (tid == 0) sbid = atomicAdd(&g_ticket, 1);
    __syncthreads();
    const int bid = sbid;
    const int i = bid * SCAN_B + tid;

    int v = (i < NN) ? g_cnt[i] : 0;
    if (i < NN) {
        float d = g_deg[i];
        g_dinv[i] = (d > 0.f) ? rsqrtf(d) : 0.f;
    }
    s[tid] = v;
    __syncthreads();
    for (int off = 1; off < SCAN_B; off <<= 1) {
        int t = (tid >= off) ? s[tid - off] : 0;
        __syncthreads();
        s[tid] += t;
        __syncthreads();
    }
    const int aggv = s[SCAN_B - 1];

    if (tid == 0) {
        if (bid == 0) {
            atomicExch(&g_tstate[0], (2u << 30) | (unsigned)aggv);
            sprev = 0;
        } else {
            atomicExch(&g_tstate[bid], (1u << 30) | (unsigned)aggv);
            int run = 0;
            for (int t = bid - 1; t >= 0; t--) {
                unsigned st;
                do { st = atomicOr(&g_tstate[t], 0u); } while ((st >> 30) == 0u);
                run += (int)(st & 0x3FFFFFFFu);
                if ((st >> 30) == 2u) break;
            }
            atomicExch(&g_tstate[bid], (2u << 30) | (unsigned)(run + aggv));
            sprev = run;
        }
    }
    __syncthreads();
    if (i < NN) {
        int off = sprev + s[tid] - v;
        g_off[i] = off;
        g_cur[i] = off;
    }
}

// Fill CSR payload from packed rc.
__global__ void fill_kernel() {
    int e = blockIdx.x * blockDim.x + threadIdx.x;
    if (e >= EE) return;
    unsigned rc = g_rc[e];
    unsigned ew = (unsigned)__half_as_ushort(g_ew[e]);
    int p = atomicAdd(&g_cur[rc >> 16], 1);
    g_epack[p] = (ew << 16) | (rc & 0xFFFFu);
}

__device__ __forceinline__ void acc8(float2* acc, uint4 v, float nm) {
    const __half2* h = (const __half2*)&v;
    #pragma unroll
    for (int q = 0; q < 4; q++) {
        float2 f = __half22float2(h[q]);
        acc[q].x += f.x * nm;
        acc[q].y += f.y * nm;
    }
}

// Gather aggregation: persistent warps, dynamic node tickets (degree-balance),
// batch-level software pipelining of the edge payload.
__global__ __launch_bounds__(256) void agg_kernel() {
    int lane = threadIdx.x & 31;

    for (;;) {
        int n;
        if (lane == 0) n = atomicAdd(&g_aticket, 1);
        n = __shfl_sync(0xffffffffu, n, 0);
        if (n >= NN) return;

        int start = g_off[n];
        int cnt   = g_cnt[n];
        float dsn = g_dinv[n];

        float2 accA[4] = {{0.f,0.f},{0.f,0.f},{0.f,0.f},{0.f,0.f}};
        float2 accB[4] = {{0.f,0.f},{0.f,0.f},{0.f,0.f},{0.f,0.f}};

        unsigned pk = 0;
        if (lane < cnt) pk = g_epack[start + lane];

        for (int base = 0; base < cnt; base += 32) {
            int m = min(32, cnt - base);
            float val = 0.f;
            if (lane < m)
                val = g_dinv[pk & 0xFFFFu]
                    * __half2float(__ushort_as_half((unsigned short)(pk >> 16)));
            unsigned pkc = pk;
            pk = 0;
            if (base + 32 + lane < cnt) pk = g_epack[start + base + 32 + lane];

            #pragma unroll 4
            for (int j = 0; j < m; j++) {
                unsigned p = __shfl_sync(0xffffffffu, pkc, j);
                float nm = __shfl_sync(0xffffffffu, val, j) * dsn;
                int r = (int)(p & 0xFFFFu);
                const uint4* xp = (const uint4*)(g_xh + (size_t)r * DD) + lane;
                uint4 v0 = xp[0];
                uint4 v1 = xp[32];
                acc8(accA, v0, nm);
                acc8(accB, v1, nm);
            }
        }
        uint4 o0, o1;
        __half2* h0 = (__half2*)&o0;
        __half2* h1 = (__half2*)&o1;
        #pragma unroll
        for (int q = 0; q < 4; q++) {
            h0[q] = __float22half2_rn(accA[q]);
            h1[q] = __float22half2_rn(accB[q]);
        }
        uint4* op = (uint4*)(g_aggh + (size_t)n * DD) + lane;
        __stcs(op, o0);
        __stcs(op + 32, o1);
    }
}

// ---------------- fp16 tensor-core GEMM: C = A @ W^T + bias ----------------
// (round-11 version: 128x256 tile, 3-stage cp.async, ldmatrix fragments)
__device__ __forceinline__ void mma_f16(float* d, const unsigned* a, const unsigned* b) {
    asm volatile(
        "mma.sync.aligned.m16n8k16.row.col.f32.f16.f16.f32 "
        "{%0,%1,%2,%3}, {%4,%5,%6,%7}, {%8,%9}, {%0,%1,%2,%3};"
        : "+f"(d[0]), "+f"(d[1]), "+f"(d[2]), "+f"(d[3])
        : "r"(a[0]), "r"(a[1]), "r"(a[2]), "r"(a[3]), "r"(b[0]), "r"(b[1]));
}
__device__ __forceinline__ void ldm_x4(unsigned& r0, unsigned& r1,
                                       unsigned& r2, unsigned& r3, unsigned addr) {
    asm volatile("ldmatrix.sync.aligned.m8n8.x4.shared.b16 {%0,%1,%2,%3}, [%4];"
                 : "=r"(r0), "=r"(r1), "=r"(r2), "=r"(r3) : "r"(addr));
}
__device__ __forceinline__ void cpa16(unsigned dst, const void* src, int sz) {
    asm volatile("cp.async.cg.shared.global [%0], [%1], 16, %2;"
                 :: "r"(dst), "l"(src), "r"(sz) : "memory");
}
__device__ __forceinline__ unsigned smem_u32(const void* p) {
    unsigned a;
    asm("{ .reg .u64 t; cvta.to.shared.u64 t, %1; cvt.u32.u64 %0, t; }" : "=r"(a) : "l"(p));
    return a;
}

#define KPH 40
#define ST_A (128 * KPH)
#define ST_B (256 * KPH)
#define STAGE_H (ST_A + ST_B)
#define GSMEM (3 * STAGE_H * 2)

__global__ __launch_bounds__(256, 1) void gemm_f16(const float* __restrict__ bias,
                                                   float* __restrict__ C,
                                                   int M) {
    extern __shared__ __half sm[];
    const unsigned smb = smem_u32(sm);

    const int tid  = threadIdx.x;
    const int lane = tid & 31;
    const int warp = tid >> 5;
    const int wm = warp & 1;
    const int wn = warp >> 1;
    const int g  = lane >> 2;
    const int tg = lane & 3;

    const int blockRow = blockIdx.y * 128;
    const int blockCol = blockIdx.x * 256;

    const int aRowOff = (lane & 7) + ((lane >> 3) & 1) * 8;
    const int aKOff   = (lane >> 4) * 8;
    const int bColOff = (lane & 7);
    const int bKOff   = ((lane >> 3) & 1) * 8;
    const int bNtHalf = (lane >> 4);

    const int lr  = tid >> 1;
    const int c0h = (tid & 1) * 16;
    const int gr  = blockRow + lr;
    const int aSz = (gr < M) ? 16 : 0;
    const __half* aSrc = g_aggh + (size_t)min(gr, M - 1) * 512 + c0h;
    const __half* bSrc = g_wh + (size_t)(blockCol + tid) * 512;

    float acc[4][8][4];
    #pragma unroll
    for (int mt = 0; mt < 4; mt++)
        #pragma unroll
        for (int nt = 0; nt < 8; nt++)
            #pragma unroll
            for (int q = 0; q < 4; q++) acc[mt][nt][q] = 0.f;

    auto load_tile = [&](int s, int ch) {
        unsigned ab = smb + (unsigned)(s * STAGE_H) * 2;
        unsigned bb = ab + (unsigned)ST_A * 2;
        const __half* ap = aSrc + ch * 32;
        cpa16(ab + (lr * KPH + c0h) * 2, ap, aSz);
        cpa16(ab + (lr * KPH + c0h + 8) * 2, ap + 8, aSz);
        const __half* bp = bSrc + ch * 32;
        #pragma unroll
        for (int j = 0; j < 4; j++)
            cpa16(bb + (tid * KPH + j * 8) * 2, bp + j * 8, 16);
        asm volatile("cp.async.commit_group;" ::: "memory");
    };

    load_tile(0, 0);
    load_tile(1, 1);

    for (int ch = 0; ch < 16; ch++) {
        const int s = ch % 3;
        if (ch + 2 < 16) asm volatile("cp.async.wait_group 1;" ::: "memory");
        else             asm volatile("cp.async.wait_group 0;" ::: "memory");
        __syncthreads();
        if (ch + 2 < 16) load_tile((ch + 2) % 3, ch + 2);

        const unsigned asb = smb + (unsigned)(s * STAGE_H) * 2;
        const unsigned bsb = asb + (unsigned)ST_A * 2;

        #pragma unroll
        for (int ks = 0; ks < 32; ks += 16) {
            unsigned a[4][4], bf[8][2];
            #pragma unroll
            for (int mt = 0; mt < 4; mt++) {
                unsigned addr = asb + (unsigned)(((wm * 64 + mt * 16 + aRowOff) * KPH
                                                 + ks + aKOff) * 2);
                ldm_x4(a[mt][0], a[mt][1], a[mt][2], a[mt][3], addr);
            }
            #pragma unroll
            for (int q = 0; q < 4; q++) {
                int col = wn * 64 + (2 * q + bNtHalf) * 8 + bColOff;
                unsigned addr = bsb + (unsigned)((col * KPH + ks + bKOff) * 2);
                unsigned r0, r1, r2, r3;
                ldm_x4(r0, r1, r2, r3, addr);
                bf[2 * q][0] = r0; bf[2 * q][1] = r1;
                bf[2 * q + 1][0] = r2; bf[2 * q + 1][1] = r3;
            }
            #pragma unroll
            for (int mt = 0; mt < 4; mt++)
                #pragma unroll
                for (int nt = 0; nt < 8; nt++)
                    mma_f16(acc[mt][nt], a[mt], bf[nt]);
        }
        __syncthreads();
    }

    #pragma unroll
    for (int mt = 0; mt < 4; mt++) {
        int r0 = blockRow + wm * 64 + mt * 16 + g;
        #pragma unroll
        for (int nt = 0; nt < 8; nt++) {
            int col = blockCol + wn * 64 + nt * 8 + tg * 2;
            float b0 = bias[col], b1 = bias[col + 1];
            if (r0 < M) {
                float2 o = make_float2(acc[mt][nt][0] + b0, acc[mt][nt][1] + b1);
                *(float2*)(C + (size_t)r0 * 512 + col) = o;
            }
            if (r0 + 8 < M) {
                float2 o = make_float2(acc[mt][nt][2] + b0, acc[mt][nt][3] + b1);
                *(float2*)(C + (size_t)(r0 + 8) * 512 + col) = o;
            }
        }
    }
}

extern "C" void kernel_launch(void* const* d_in, const int* in_sizes, int n_in,
                              void* d_out, int out_size) {
    const float* x  = (const float*)d_in[0];
    const void*  ei = d_in[1];
    const float* ea = (const float*)d_in[2];
    const float* lw = (const float*)d_in[3];
    const float* lb = (const float*)d_in[4];
    const float* cw = (const float*)d_in[5];
    const float* cb = (const float*)d_in[6];
    float* out = (float*)d_out;

    cudaFuncSetAttribute(gemm_f16, cudaFuncAttributeMaxDynamicSharedMemorySize, GSMEM);

    prep_convert<<<(NN * DD / 8 + 255) / 256, 256>>>(x, lw);
    prep_meta<<<(NN + 255) / 256, 256>>>(ei);
    edge_pass1<<<(EE + 255) / 256, 256>>>(ei, ea, cw, cb);
    scan_all<<<NBLK, SCAN_B>>>();
    fill_kernel<<<(EE + 255) / 256, 256>>>();
    agg_kernel<<<1184, 256>>>();

    dim3 grid(2, (NN + 127) / 128);
    gemm_f16<<<grid, 256, GSMEM>>>(lb, out, NN);
}

// round 15
// speedup vs baseline: 1.0156x; 1.0003x over previous
#include <cuda_runtime.h>
#include <cuda_fp16.h>
#include <math.h>

#define NN 50000
#define EE 800000
#define DD 512

// ---------------- scratch (device globals; no allocations) ----------------
__device__ __align__(16) __half g_xh[(size_t)NN * DD];    // x in fp16
__device__ __align__(16) __half g_aggh[(size_t)NN * DD];  // aggregated, fp16
__device__ __align__(16) __half g_wh[512 * 512];          // W in fp16
__device__ __align__(16) float g_deg[NN];
__device__ __align__(16) float g_dinv[NN];
__device__ __align__(16) __half g_ew[EE];                 // edge confidence fp16
__device__ __align__(16) unsigned g_rc[EE];               // (col<<16)|row
__device__ int      g_cnt[NN];
__device__ int      g_off[NN];
__device__ int      g_cur[NN];
__device__ unsigned g_epack[EE];      // (ew_fp16 << 16) | src_row
__device__ unsigned g_tstate[64];     // lookback state
__device__ int      g_ticket;
__device__ int      g_idx64;

#define SCAN_T   512     // threads per scan block
#define SCAN_TILE 1024   // elements per scan block (2 per thread)
#define NBLK     49      // ceil(50000/1024)

// ---------------- edge-index dtype-agnostic fetch ----------------
__device__ __forceinline__ long long edge_idx(const void* p, long long i) {
    if (g_idx64) return ((const long long*)p)[i];
    return (long long)((const int*)p)[i];
}

__device__ __forceinline__ uint4 cvt8(float4 f0, float4 f1) {
    uint4 o;
    __half2* oh = (__half2*)&o;
    oh[0] = __float22half2_rn(make_float2(f0.x, f0.y));
    oh[1] = __float22half2_rn(make_float2(f0.z, f0.w));
    oh[2] = __float22half2_rn(make_float2(f1.x, f1.y));
    oh[3] = __float22half2_rn(make_float2(f1.z, f1.w));
    return o;
}

// Convert x and W to fp16.
__global__ void prep_convert(const float* __restrict__ x, const float* __restrict__ W) {
    size_t i = (size_t)blockIdx.x * blockDim.x + threadIdx.x;
    if (i < 512 * 512 / 8)
        ((uint4*)g_wh)[i] = cvt8(((const float4*)W)[i * 2], ((const float4*)W)[i * 2 + 1]);
    if (i < (size_t)NN * DD / 8)
        ((uint4*)g_xh)[i] = cvt8(((const float4*)x)[i * 2], ((const float4*)x)[i * 2 + 1]);
}

// Edge-chain head: detect idx dtype, zero counters and scan state.
__global__ void prep_meta(const void* __restrict__ ei) {
    int i = blockIdx.x * blockDim.x + threadIdx.x;
    if (i == 0) {
        const long long* p = (const long long*)ei;
        int ok = 1;
        for (int j = 0; j < 64; j++) {
            long long v = p[j];
            if (v < 0 || v >= NN) { ok = 0; break; }
        }
        g_idx64 = ok;
        g_ticket = 0;
    }
    if (i < 64) g_tstate[i] = 0;
    if (i < NN) { g_deg[i] = 0.f; g_cnt[i] = 0; }
}

__global__ void edge_pass1(const void* __restrict__ ei,
                           const float* __restrict__ ea,
                           const float* __restrict__ cw,
                           const float* __restrict__ cb) {
    int e = blockIdx.x * blockDim.x + threadIdx.x;
    if (e >= EE) return;
    long long r = edge_idx(ei, e);
    long long c = edge_idx(ei, (long long)EE + e);
    atomicAdd(&g_deg[r], 1.0f);
    atomicAdd(&g_cnt[c], 1);
    g_rc[e] = ((unsigned)c << 16) | (unsigned)r;
    float z = ea[e * 3 + 0] * cw[0] + ea[e * 3 + 1] * cw[1]
            + ea[e * 3 + 2] * cw[2] + cb[0];
    g_ew[e] = __float2half(1.0f / (1.0f + expf(-z)));
}

// Single-launch decoupled-lookback scan, shuffle-based (2 barriers/block),
// 1024 elems per block; fuses node_dinv + cursor init.
__global__ __launch_bounds__(SCAN_T) void scan_all() {
    __shared__ int wsum[16];
    __shared__ int sTot, sbid, sprev;
    const int tid  = threadIdx.x;
    const int lane = tid & 31;
    const int wid  = tid >> 5;

    if (tid == 0) sbid = atomicAdd(&g_ticket, 1);
    __syncthreads();
    const int bid = sbid;
    const int i0 = bid * SCAN_TILE + tid * 2;

    int c0 = (i0 < NN) ? g_cnt[i0] : 0;
    int c1 = (i0 + 1 < NN) ? g_cnt[i0 + 1] : 0;
    if (i0 < NN) {
        float d = g_deg[i0];
        g_dinv[i0] = (d > 0.f) ? rsqrtf(d) : 0.f;
    }
    if (i0 + 1 < NN) {
        float d = g_deg[i0 + 1];
        g_dinv[i0 + 1] = (d > 0.f) ? rsqrtf(d) : 0.f;
    }
    int sum = c0 + c1;

    // warp inclusive scan
    int incl = sum;
    #pragma unroll
    for (int o = 1; o < 32; o <<= 1) {
        int t = __shfl_up_sync(0xffffffffu, incl, o);
        if (lane >= o) incl += t;
    }
    if (lane == 31) wsum[wid] = incl;
    __syncthreads();

    // warp 0 scans the 16 warp sums
    if (wid == 0 && lane < 16) {
        int v = wsum[lane];
        int s = v;
        #pragma unroll
        for (int o = 1; o < 16; o <<= 1) {
            int t = __shfl_up_sync(0x0000ffffu, s, o);
            if (lane >= o) s += t;
        }
        wsum[lane] = s - v;               // exclusive warp base
        if (lane == 15) sTot = s;         // block total
    }
    __syncthreads();

    const int excl = wsum[wid] + incl - sum;  // block-local exclusive prefix
    const int aggv = sTot;

    if (tid == 0) {
        if (bid == 0) {
            atomicExch(&g_tstate[0], (2u << 30) | (unsigned)aggv);
            sprev = 0;
        } else {
            atomicExch(&g_tstate[bid], (1u << 30) | (unsigned)aggv);
            int run = 0;
            for (int t = bid - 1; t >= 0; t--) {
                unsigned st;
                do { st = atomicOr(&g_tstate[t], 0u); } while ((st >> 30) == 0u);
                run += (int)(st & 0x3FFFFFFFu);
                if ((st >> 30) == 2u) break;
            }
            atomicExch(&g_tstate[bid], (2u << 30) | (unsigned)(run + aggv));
            sprev = run;
        }
    }
    __syncthreads();
    if (i0 < NN) {
        int o = sprev + excl;
        g_off[i0] = o;
        g_cur[i0] = o;
    }
    if (i0 + 1 < NN) {
        int o = sprev + excl + c0;
        g_off[i0 + 1] = o;
        g_cur[i0 + 1] = o;
    }
}

// Fill CSR payload from packed rc.
__global__ void fill_kernel() {
    int e = blockIdx.x * blockDim.x + threadIdx.x;
    if (e >= EE) return;
    unsigned rc = g_rc[e];
    unsigned ew = (unsigned)__half_as_ushort(g_ew[e]);
    int p = atomicAdd(&g_cur[rc >> 16], 1);
    g_epack[p] = (ew << 16) | (rc & 0xFFFFu);
}

__device__ __forceinline__ void acc8(float2* acc, uint4 v, float nm) {
    const __half2* h = (const __half2*)&v;
    #pragma unroll
    for (int q = 0; q < 4; q++) {
        float2 f = __half22float2(h[q]);
        acc[q].x += f.x * nm;
        acc[q].y += f.y * nm;
    }
}

// Gather aggregation: one WARP per node, batch-level software pipelining.
// Output stores are NORMAL (not streaming) so g_aggh stays L2-resident for
// the GEMM's two A-tile passes (x + agg both fit in 126 MB L2).
__global__ __launch_bounds__(256) void agg_kernel() {
    int warp = threadIdx.x >> 5;
    int lane = threadIdx.x & 31;
    int n = blockIdx.x * 8 + warp;
    if (n >= NN) return;
    int start = g_off[n];
    int cnt   = g_cnt[n];
    float dsn = g_dinv[n];

    float2 accA[4] = {{0.f,0.f},{0.f,0.f},{0.f,0.f},{0.f,0.f}};
    float2 accB[4] = {{0.f,0.f},{0.f,0.f},{0.f,0.f},{0.f,0.f}};

    unsigned pk = 0;
    if (lane < cnt) pk = g_epack[start + lane];

    for (int base = 0; base < cnt; base += 32) {
        int m = min(32, cnt - base);
        float val = 0.f;
        if (lane < m)
            val = g_dinv[pk & 0xFFFFu]
                * __half2float(__ushort_as_half((unsigned short)(pk >> 16)));
        unsigned pkc = pk;
        pk = 0;
        if (base + 32 + lane < cnt) pk = g_epack[start + base + 32 + lane];

        #pragma unroll 4
        for (int j = 0; j < m; j++) {
            unsigned p = __shfl_sync(0xffffffffu, pkc, j);
            float nm = __shfl_sync(0xffffffffu, val, j) * dsn;
            int r = (int)(p & 0xFFFFu);
            const uint4* xp = (const uint4*)(g_xh + (size_t)r * DD) + lane;
            uint4 v0 = xp[0];
            uint4 v1 = xp[32];
            acc8(accA, v0, nm);
            acc8(accB, v1, nm);
        }
    }
    uint4 o0, o1;
    __half2* h0 = (__half2*)&o0;
    __half2* h1 = (__half2*)&o1;
    #pragma unroll
    for (int q = 0; q < 4; q++) {
        h0[q] = __float22half2_rn(accA[q]);
        h1[q] = __float22half2_rn(accB[q]);
    }
    uint4* op = (uint4*)(g_aggh + (size_t)n * DD) + lane;
    op[0]  = o0;
    op[32] = o1;
}

// ---------------- fp16 tensor-core GEMM: C = A @ W^T + bias ----------------
__device__ __forceinline__ void mma_f16(float* d, const unsigned* a, const unsigned* b) {
    asm volatile(
        "mma.sync.aligned.m16n8k16.row.col.f32.f16.f16.f32 "
        "{%0,%1,%2,%3}, {%4,%5,%6,%7}, {%8,%9}, {%0,%1,%2,%3};"
        : "+f"(d[0]), "+f"(d[1]), "+f"(d[2]), "+f"(d[3])
        : "r"(a[0]), "r"(a[1]), "r"(a[2]), "r"(a[3]), "r"(b[0]), "r"(b[1]));
}
__device__ __forceinline__ void ldm_x4(unsigned& r0, unsigned& r1,
                                       unsigned& r2, unsigned& r3, unsigned addr) {
    asm volatile("ldmatrix.sync.aligned.m8n8.x4.shared.b16 {%0,%1,%2,%3}, [%4];"
                 : "=r"(r0), "=r"(r1), "=r"(r2), "=r"(r3) : "r"(addr));
}
__device__ __forceinline__ void cpa16(unsigned dst, const void* src, int sz) {
    asm volatile("cp.async.cg.shared.global [%0], [%1], 16, %2;"
                 :: "r"(dst), "l"(src), "r"(sz) : "memory");
}
__device__ __forceinline__ unsigned smem_u32(const void* p) {
    unsigned a;
    asm("{ .reg .u64 t; cvta.to.shared.u64 t, %1; cvt.u32.u64 %0, t; }" : "=r"(a) : "l"(p));
    return a;
}

#define KPH 40
#define ST_A (128 * KPH)
#define ST_B (256 * KPH)
#define STAGE_H (ST_A + ST_B)
#define GSMEM (3 * STAGE_H * 2)

__global__ __launch_bounds__(256, 1) void gemm_f16(const float* __restrict__ bias,
                                                   float* __restrict__ C,
                                                   int M) {
    extern __shared__ __half sm[];
    const unsigned smb = smem_u32(sm);

    const int tid  = threadIdx.x;
    const int lane = tid & 31;
    const int warp = tid >> 5;
    const int wm = warp & 1;
    const int wn = warp >> 1;
    const int g  = lane >> 2;
    const int tg = lane & 3;

    const int blockRow = blockIdx.y * 128;
    const int blockCol = blockIdx.x * 256;

    const int aRowOff = (lane & 7) + ((lane >> 3) & 1) * 8;
    const int aKOff   = (lane >> 4) * 8;
    const int bColOff = (lane & 7);
    const int bKOff   = ((lane >> 3) & 1) * 8;
    const int bNtHalf = (lane >> 4);

    const int lr  = tid >> 1;
    const int c0h = (tid & 1) * 16;
    const int gr  = blockRow + lr;
    const int aSz = (gr < M) ? 16 : 0;
    const __half* aSrc = g_aggh + (size_t)min(gr, M - 1) * 512 + c0h;
    const __half* bSrc = g_wh + (size_t)(blockCol + tid) * 512;

    float acc[4][8][4];
    #pragma unroll
    for (int mt = 0; mt < 4; mt++)
        #pragma unroll
        for (int nt = 0; nt < 8; nt++)
            #pragma unroll
            for (int q = 0; q < 4; q++) acc[mt][nt][q] = 0.f;

    auto load_tile = [&](int s, int ch) {
        unsigned ab = smb + (unsigned)(s * STAGE_H) * 2;
        unsigned bb = ab + (unsigned)ST_A * 2;
        const __half* ap = aSrc + ch * 32;
        cpa16(ab + (lr * KPH + c0h) * 2, ap, aSz);
        cpa16(ab + (lr * KPH + c0h + 8) * 2, ap + 8, aSz);
        const __half* bp = bSrc + ch * 32;
        #pragma unroll
        for (int j = 0; j < 4; j++)
            cpa16(bb + (tid * KPH + j * 8) * 2, bp + j * 8, 16);
        asm volatile("cp.async.commit_group;" ::: "memory");
    };

    load_tile(0, 0);
    load_tile(1, 1);

    for (int ch = 0; ch < 16; ch++) {
        const int s = ch % 3;
        if (ch + 2 < 16) asm volatile("cp.async.wait_group 1;" ::: "memory");
        else             asm volatile("cp.async.wait_group 0;" ::: "memory");
        __syncthreads();
        if (ch + 2 < 16) load_tile((ch + 2) % 3, ch + 2);

        const unsigned asb = smb + (unsigned)(s * STAGE_H) * 2;
        const unsigned bsb = asb + (unsigned)ST_A * 2;

        #pragma unroll
        for (int ks = 0; ks < 32; ks += 16) {
            unsigned a[4][4], bf[8][2];
            #pragma unroll
            for (int mt = 0; mt < 4; mt++) {
                unsigned addr = asb + (unsigned)(((wm * 64 + mt * 16 + aRowOff) * KPH
                                                 + ks + aKOff) * 2);
                ldm_x4(a[mt][0], a[mt][1], a[mt][2], a[mt][3], addr);
            }
            #pragma unroll
            for (int q = 0; q < 4; q++) {
                int col = wn * 64 + (2 * q + bNtHalf) * 8 + bColOff;
                unsigned addr = bsb + (unsigned)((col * KPH + ks + bKOff) * 2);
                unsigned r0, r1, r2, r3;
                ldm_x4(r0, r1, r2, r3, addr);
                bf[2 * q][0] = r0; bf[2 * q][1] = r1;
                bf[2 * q + 1][0] = r2; bf[2 * q + 1][1] = r3;
            }
            #pragma unroll
            for (int mt = 0; mt < 4; mt++)
                #pragma unroll
                for (int nt = 0; nt < 8; nt++)
                    mma_f16(acc[mt][nt], a[mt], bf[nt]);
        }
        __syncthreads();
    }

    #pragma unroll
    for (int mt = 0; mt < 4; mt++) {
        int r0 = blockRow + wm * 64 + mt * 16 + g;
        #pragma unroll
        for (int nt = 0; nt < 8; nt++) {
            int col = blockCol + wn * 64 + nt * 8 + tg * 2;
            float b0 = bias[col], b1 = bias[col + 1];
            if (r0 < M) {
                float2 o = make_float2(acc[mt][nt][0] + b0, acc[mt][nt][1] + b1);
                __stcs((float2*)(C + (size_t)r0 * 512 + col), o);
            }
            if (r0 + 8 < M) {
                float2 o = make_float2(acc[mt][nt][2] + b0, acc[mt][nt][3] + b1);
                __stcs((float2*)(C + (size_t)(r0 + 8) * 512 + col), o);
            }
        }
    }
}

extern "C" void kernel_launch(void* const* d_in, const int* in_sizes, int n_in,
                              void* d_out, int out_size) {
    const float* x  = (const float*)d_in[0];
    const void*  ei = d_in[1];
    const float* ea = (const float*)d_in[2];
    const float* lw = (const float*)d_in[3];
    const float* lb = (const float*)d_in[4];
    const float* cw = (const float*)d_in[5];
    const float* cb = (const float*)d_in[6];
    float* out = (float*)d_out;

    cudaFuncSetAttribute(gemm_f16, cudaFuncAttributeMaxDynamicSharedMemorySize, GSMEM);

    prep_convert<<<(NN * DD / 8 + 255) / 256, 256>>>(x, lw);
    prep_meta<<<(NN + 255) / 256, 256>>>(ei);
    edge_pass1<<<(EE + 255) / 256, 256>>>(ei, ea, cw, cb);
    scan_all<<<NBLK, SCAN_T>>>();
    fill_kernel<<<(EE + 255) / 256, 256>>>();
    agg_kernel<<<(NN + 7) / 8, 256>>>();

    dim3 grid(2, (NN + 127) / 128);
    gemm_f16<<<grid, 256, GSMEM>>>(lb, out, NN);
}

// round 16
// speedup vs baseline: 1.0215x; 1.0058x over previous
#include <cuda_runtime.h>
#include <cuda_fp16.h>
#include <math.h>

#define NN 50000
#define EE 800000
#define DD 512

// ---------------- scratch (device globals; no allocations) ----------------
__device__ __align__(16) __half g_xh[(size_t)NN * DD];    // x in fp16
__device__ __align__(16) __half g_aggh[(size_t)NN * DD];  // aggregated, fp16
__device__ __align__(16) __half g_wh[512 * 512];          // W in fp16
__device__ __align__(16) float g_deg[NN];
__device__ __align__(16) float g_dinv[NN];
__device__ __align__(16) __half g_ew[EE];                 // edge confidence fp16
__device__ __align__(16) unsigned g_rc[EE];               // (col<<16)|row
__device__ __align__(16) int g_rank[EE];                  // rank within dest bucket
__device__ int      g_cnt[NN];
__device__ int      g_off[NN];
__device__ unsigned g_epack[EE];      // (ew_fp16 << 16) | src_row
__device__ unsigned g_tstate[64];     // lookback state
__device__ int      g_ticket;
__device__ int      g_idx64;

#define SCAN_T   512     // threads per scan block
#define SCAN_TILE 1024   // elements per scan block (2 per thread)
#define NBLK     49      // ceil(50000/1024)

// ---------------- edge-index dtype-agnostic fetch ----------------
__device__ __forceinline__ long long edge_idx(const void* p, long long i) {
    if (g_idx64) return ((const long long*)p)[i];
    return (long long)((const int*)p)[i];
}

__device__ __forceinline__ uint4 cvt8(float4 f0, float4 f1) {
    uint4 o;
    __half2* oh = (__half2*)&o;
    oh[0] = __float22half2_rn(make_float2(f0.x, f0.y));
    oh[1] = __float22half2_rn(make_float2(f0.z, f0.w));
    oh[2] = __float22half2_rn(make_float2(f1.x, f1.y));
    oh[3] = __float22half2_rn(make_float2(f1.z, f1.w));
    return o;
}

// Convert x and W to fp16.
__global__ void prep_convert(const float* __restrict__ x, const float* __restrict__ W) {
    size_t i = (size_t)blockIdx.x * blockDim.x + threadIdx.x;
    if (i < 512 * 512 / 8)
        ((uint4*)g_wh)[i] = cvt8(((const float4*)W)[i * 2], ((const float4*)W)[i * 2 + 1]);
    if (i < (size_t)NN * DD / 8)
        ((uint4*)g_xh)[i] = cvt8(((const float4*)x)[i * 2], ((const float4*)x)[i * 2 + 1]);
}

// Edge-chain head: detect idx dtype, zero counters and scan state.
__global__ void prep_meta(const void* __restrict__ ei) {
    int i = blockIdx.x * blockDim.x + threadIdx.x;
    if (i == 0) {
        const long long* p = (const long long*)ei;
        int ok = 1;
        for (int j = 0; j < 64; j++) {
            long long v = p[j];
            if (v < 0 || v >= NN) { ok = 0; break; }
        }
        g_idx64 = ok;
        g_ticket = 0;
    }
    if (i < 64) g_tstate[i] = 0;
    if (i < NN) { g_deg[i] = 0.f; g_cnt[i] = 0; }
}

// The cnt atomic's RETURN VALUE is this edge's rank within its destination
// bucket — saved so fill_kernel needs no atomics at all.
__global__ void edge_pass1(const void* __restrict__ ei,
                           const float* __restrict__ ea,
                           const float* __restrict__ cw,
                           const float* __restrict__ cb) {
    int e = blockIdx.x * blockDim.x + threadIdx.x;
    if (e >= EE) return;
    long long r = edge_idx(ei, e);
    long long c = edge_idx(ei, (long long)EE + e);
    atomicAdd(&g_deg[r], 1.0f);
    g_rank[e] = atomicAdd(&g_cnt[c], 1);
    g_rc[e] = ((unsigned)c << 16) | (unsigned)r;
    float z = ea[e * 3 + 0] * cw[0] + ea[e * 3 + 1] * cw[1]
            + ea[e * 3 + 2] * cw[2] + cb[0];
    g_ew[e] = __float2half(1.0f / (1.0f + expf(-z)));
}

// Single-launch decoupled-lookback scan, shuffle-based (2 barriers/block),
// 1024 elems per block; fuses node_dinv.
__global__ __launch_bounds__(SCAN_T) void scan_all() {
    __shared__ int wsum[16];
    __shared__ int sTot, sbid, sprev;
    const int tid  = threadIdx.x;
    const int lane = tid & 31;
    const int wid  = tid >> 5;

    if (tid == 0) sbid = atomicAdd(&g_ticket, 1);
    __syncthreads();
    const int bid = sbid;
    const int i0 = bid * SCAN_TILE + tid * 2;

    int c0 = (i0 < NN) ? g_cnt[i0] : 0;
    int c1 = (i0 + 1 < NN) ? g_cnt[i0 + 1] : 0;
    if (i0 < NN) {
        float d = g_deg[i0];
        g_dinv[i0] = (d > 0.f) ? rsqrtf(d) : 0.f;
    }
    if (i0 + 1 < NN) {
        float d = g_deg[i0 + 1];
        g_dinv[i0 + 1] = (d > 0.f) ? rsqrtf(d) : 0.f;
    }
    int sum = c0 + c1;

    int incl = sum;
    #pragma unroll
    for (int o = 1; o < 32; o <<= 1) {
        int t = __shfl_up_sync(0xffffffffu, incl, o);
        if (lane >= o) incl += t;
    }
    if (lane == 31) wsum[wid] = incl;
    __syncthreads();

    if (wid == 0 && lane < 16) {
        int v = wsum[lane];
        int s = v;
        #pragma unroll
        for (int o = 1; o < 16; o <<= 1) {
            int t = __shfl_up_sync(0x0000ffffu, s, o);
            if (lane >= o) s += t;
        }
        wsum[lane] = s - v;
        if (lane == 15) sTot = s;
    }
    __syncthreads();

    const int excl = wsum[wid] + incl - sum;
    const int aggv = sTot;

    if (tid == 0) {
        if (bid == 0) {
            atomicExch(&g_tstate[0], (2u << 30) | (unsigned)aggv);
            sprev = 0;
        } else {
            atomicExch(&g_tstate[bid], (1u << 30) | (unsigned)aggv);
            int run = 0;
            for (int t = bid - 1; t >= 0; t--) {
                unsigned st;
                do { st = atomicOr(&g_tstate[t], 0u); } while ((st >> 30) == 0u);
                run += (int)(st & 0x3FFFFFFFu);
                if ((st >> 30) == 2u) break;
            }
            atomicExch(&g_tstate[bid], (2u << 30) | (unsigned)(run + aggv));
            sprev = run;
        }
    }
    __syncthreads();
    if (i0 < NN) g_off[i0] = sprev + excl;
    if (i0 + 1 < NN) g_off[i0 + 1] = sprev + excl + c0;
}

// Fill CSR payload: NO atomics — slot = off[col] + rank (precomputed).
__global__ void fill_kernel() {
    int e = blockIdx.x * blockDim.x + threadIdx.x;
    if (e >= EE) return;
    unsigned rc = g_rc[e];
    unsigned ew = (unsigned)__half_as_ushort(g_ew[e]);
    int p = g_off[rc >> 16] + g_rank[e];
    g_epack[p] = (ew << 16) | (rc & 0xFFFFu);
}

__device__ __forceinline__ void acc8(float2* acc, uint4 v, float nm) {
    const __half2* h = (const __half2*)&v;
    #pragma unroll
    for (int q = 0; q < 4; q++) {
        float2 f = __half22float2(h[q]);
        acc[q].x += f.x * nm;
        acc[q].y += f.y * nm;
    }
}

// Gather aggregation: one WARP per node, batch-level software pipelining.
__global__ __launch_bounds__(256) void agg_kernel() {
    int warp = threadIdx.x >> 5;
    int lane = threadIdx.x & 31;
    int n = blockIdx.x * 8 + warp;
    if (n >= NN) return;
    int start = g_off[n];
    int cnt   = g_cnt[n];
    float dsn = g_dinv[n];

    float2 accA[4] = {{0.f,0.f},{0.f,0.f},{0.f,0.f},{0.f,0.f}};
    float2 accB[4] = {{0.f,0.f},{0.f,0.f},{0.f,0.f},{0.f,0.f}};

    unsigned pk = 0;
    if (lane < cnt) pk = g_epack[start + lane];

    for (int base = 0; base < cnt; base += 32) {
        int m = min(32, cnt - base);
        float val = 0.f;
        if (lane < m)
            val = g_dinv[pk & 0xFFFFu]
                * __half2float(__ushort_as_half((unsigned short)(pk >> 16)));
        unsigned pkc = pk;
        pk = 0;
        if (base + 32 + lane < cnt) pk = g_epack[start + base + 32 + lane];

        #pragma unroll 4
        for (int j = 0; j < m; j++) {
            unsigned p = __shfl_sync(0xffffffffu, pkc, j);
            float nm = __shfl_sync(0xffffffffu, val, j) * dsn;
            int r = (int)(p & 0xFFFFu);
            const uint4* xp = (const uint4*)(g_xh + (size_t)r * DD) + lane;
            uint4 v0 = xp[0];
            uint4 v1 = xp[32];
            acc8(accA, v0, nm);
            acc8(accB, v1, nm);
        }
    }
    uint4 o0, o1;
    __half2* h0 = (__half2*)&o0;
    __half2* h1 = (__half2*)&o1;
    #pragma unroll
    for (int q = 0; q < 4; q++) {
        h0[q] = __float22half2_rn(accA[q]);
        h1[q] = __float22half2_rn(accB[q]);
    }
    uint4* op = (uint4*)(g_aggh + (size_t)n * DD) + lane;
    op[0]  = o0;
    op[32] = o1;
}

// ---------------- fp16 tensor-core GEMM: C = A @ W^T + bias ----------------
__device__ __forceinline__ void mma_f16(float* d, const unsigned* a, const unsigned* b) {
    asm volatile(
        "mma.sync.aligned.m16n8k16.row.col.f32.f16.f16.f32 "
        "{%0,%1,%2,%3}, {%4,%5,%6,%7}, {%8,%9}, {%0,%1,%2,%3};"
        : "+f"(d[0]), "+f"(d[1]), "+f"(d[2]), "+f"(d[3])
        : "r"(a[0]), "r"(a[1]), "r"(a[2]), "r"(a[3]), "r"(b[0]), "r"(b[1]));
}
__device__ __forceinline__ void ldm_x4(unsigned& r0, unsigned& r1,
                                       unsigned& r2, unsigned& r3, unsigned addr) {
    asm volatile("ldmatrix.sync.aligned.m8n8.x4.shared.b16 {%0,%1,%2,%3}, [%4];"
                 : "=r"(r0), "=r"(r1), "=r"(r2), "=r"(r3) : "r"(addr));
}
__device__ __forceinline__ void cpa16(unsigned dst, const void* src, int sz) {
    asm volatile("cp.async.cg.shared.global [%0], [%1], 16, %2;"
                 :: "r"(dst), "l"(src), "r"(sz) : "memory");
}
__device__ __forceinline__ unsigned smem_u32(const void* p) {
    unsigned a;
    asm("{ .reg .u64 t; cvta.to.shared.u64 t, %1; cvt.u32.u64 %0, t; }" : "=r"(a) : "l"(p));
    return a;
}

#define KPH 40
#define ST_A (128 * KPH)
#define ST_B (256 * KPH)
#define STAGE_H (ST_A + ST_B)
#define GSMEM (3 * STAGE_H * 2)

__global__ __launch_bounds__(256, 1) void gemm_f16(const float* __restrict__ bias,
                                                   float* __restrict__ C,
                                                   int M) {
    extern __shared__ __half sm[];
    const unsigned smb = smem_u32(sm);

    const int tid  = threadIdx.x;
    const int lane = tid & 31;
    const int warp = tid >> 5;
    const int wm = warp & 1;
    const int wn = warp >> 1;
    const int g  = lane >> 2;
    const int tg = lane & 3;

    const int blockRow = blockIdx.y * 128;
    const int blockCol = blockIdx.x * 256;

    const int aRowOff = (lane & 7) + ((lane >> 3) & 1) * 8;
    const int aKOff   = (lane >> 4) * 8;
    const int bColOff = (lane & 7);
    const int bKOff   = ((lane >> 3) & 1) * 8;
    const int bNtHalf = (lane >> 4);

    const int lr  = tid >> 1;
    const int c0h = (tid & 1) * 16;
    const int gr  = blockRow + lr;
    const int aSz = (gr < M) ? 16 : 0;
    const __half* aSrc = g_aggh + (size_t)min(gr, M - 1) * 512 + c0h;
    const __half* bSrc = g_wh + (size_t)(blockCol + tid) * 512;

    float acc[4][8][4];
    #pragma unroll
    for (int mt = 0; mt < 4; mt++)
        #pragma unroll
        for (int nt = 0; nt < 8; nt++)
            #pragma unroll
            for (int q = 0; q < 4; q++) acc[mt][nt][q] = 0.f;

    auto load_tile = [&](int s, int ch) {
        unsigned ab = smb + (unsigned)(s * STAGE_H) * 2;
        unsigned bb = ab + (unsigned)ST_A * 2;
        const __half* ap = aSrc + ch * 32;
        cpa16(ab + (lr * KPH + c0h) * 2, ap, aSz);
        cpa16(ab + (lr * KPH + c0h + 8) * 2, ap + 8, aSz);
        const __half* bp = bSrc + ch * 32;
        #pragma unroll
        for (int j = 0; j < 4; j++)
            cpa16(bb + (tid * KPH + j * 8) * 2, bp + j * 8, 16);
        asm volatile("cp.async.commit_group;" ::: "memory");
    };

    load_tile(0, 0);
    load_tile(1, 1);

    for (int ch = 0; ch < 16; ch++) {
        const int s = ch % 3;
        if (ch + 2 < 16) asm volatile("cp.async.wait_group 1;" ::: "memory");
        else             asm volatile("cp.async.wait_group 0;" ::: "memory");
        __syncthreads();
        if (ch + 2 < 16) load_tile((ch + 2) % 3, ch + 2);

        const unsigned asb = smb + (unsigned)(s * STAGE_H) * 2;
        const unsigned bsb = asb + (unsigned)ST_A * 2;

        #pragma unroll
        for (int ks = 0; ks < 32; ks += 16) {
            unsigned a[4][4], bf[8][2];
            #pragma unroll
            for (int mt = 0; mt < 4; mt++) {
                unsigned addr = asb + (unsigned)(((wm * 64 + mt * 16 + aRowOff) * KPH
                                                 + ks + aKOff) * 2);
                ldm_x4(a[mt][0], a[mt][1], a[mt][2], a[mt][3], addr);
            }
            #pragma unroll
            for (int q = 0; q < 4; q++) {
                int col = wn * 64 + (2 * q + bNtHalf) * 8 + bColOff;
                unsigned addr = bsb + (unsigned)((col * KPH + ks + bKOff) * 2);
                unsigned r0, r1, r2, r3;
                ldm_x4(r0, r1, r2, r3, addr);
                bf[2 * q][0] = r0; bf[2 * q][1] = r1;
                bf[2 * q + 1][0] = r2; bf[2 * q + 1][1] = r3;
            }
            #pragma unroll
            for (int mt = 0; mt < 4; mt++)
                #pragma unroll
                for (int nt = 0; nt < 8; nt++)
                    mma_f16(acc[mt][nt], a[mt], bf[nt]);
        }
        __syncthreads();
    }

    #pragma unroll
    for (int mt = 0; mt < 4; mt++) {
        int r0 = blockRow + wm * 64 + mt * 16 + g;
        #pragma unroll
        for (int nt = 0; nt < 8; nt++) {
            int col = blockCol + wn * 64 + nt * 8 + tg * 2;
            float b0 = bias[col], b1 = bias[col + 1];
            if (r0 < M) {
                float2 o = make_float2(acc[mt][nt][0] + b0, acc[mt][nt][1] + b1);
                __stcs((float2*)(C + (size_t)r0 * 512 + col), o);
            }
            if (r0 + 8 < M) {
                float2 o = make_float2(acc[mt][nt][2] + b0, acc[mt][nt][3] + b1);
                __stcs((float2*)(C + (size_t)(r0 + 8) * 512 + col), o);
            }
        }
    }
}

extern "C" void kernel_launch(void* const* d_in, const int* in_sizes, int n_in,
                              void* d_out, int out_size) {
    const float* x  = (const float*)d_in[0];
    const void*  ei = d_in[1];
    const float* ea = (const float*)d_in[2];
    const float* lw = (const float*)d_in[3];
    const float* lb = (const float*)d_in[4];
    const float* cw = (const float*)d_in[5];
    const float* cb = (const float*)d_in[6];
    float* out = (float*)d_out;

    cudaFuncSetAttribute(gemm_f16, cudaFuncAttributeMaxDynamicSharedMemorySize, GSMEM);

    prep_convert<<<(NN * DD / 8 + 255) / 256, 256>>>(x, lw);
    prep_meta<<<(NN + 255) / 256, 256>>>(ei);
    edge_pass1<<<(EE + 255) / 256, 256>>>(ei, ea, cw, cb);
    scan_all<<<NBLK, SCAN_T>>>();
    fill_kernel<<<(EE + 255) / 256, 256>>>();
    agg_kernel<<<(NN + 7) / 8, 256>>>();

    dim3 grid(2, (NN + 127) / 128);
    gemm_f16<<<grid, 256, GSMEM>>>(lb, out, NN);
}